// round 15
// baseline (speedup 1.0000x reference)
#include <cuda_runtime.h>
#include <cuda_bf16.h>
#include <math.h>
#include <stdint.h>

#define Bc 2
#define Sc 2048
#define Dc 1024
#define Hc 16
#define HDc 64
#define Rc 128
#define NBc 32
#define TOPKc 4

// ---------------- scratch (no device allocs) ----------------
__device__ float rE_q[Bc*Sc*Dc];
__device__ float rE_kv[Bc*Sc*2*Dc];
__device__ float rE_scores[Bc*NBc];
__device__ int   rE_sel[Bc*TOPKc];
__device__ float rE_vmean[Bc*Dc];
__device__ float rE_cos[Sc*32];
__device__ float rE_sin[Sc*32];
// bf16 hi/lo splits
__device__ __nv_bfloat16 rE_xh[Bc*Sc*Dc],   rE_xl[Bc*Sc*Dc];
__device__ __nv_bfloat16 rE_wqh[Dc*Dc],     rE_wql[Dc*Dc];
__device__ __nv_bfloat16 rE_wkdh[Rc*Dc],    rE_wkdl[Rc*Dc];
__device__ __nv_bfloat16 rE_wkuh[2*Dc*Rc],  rE_wkul[2*Dc*Rc];
__device__ __nv_bfloat16 rE_woh[Dc*Dc],     rE_wol[Dc*Dc];
__device__ __nv_bfloat16 rE_lath[Bc*Sc*Rc], rE_latl[Bc*Sc*Rc];
__device__ __nv_bfloat16 rE_aoh[Bc*Sc*Dc],  rE_aol[Bc*Sc*Dc];

// ---------------- helpers ----------------
__device__ __forceinline__ uint32_t rE_smem_u32(const void* p) {
    uint32_t a;
    asm("{ .reg .u64 t; cvta.to.shared.u64 t, %1; cvt.u32.u64 %0, t; }" : "=r"(a) : "l"(p));
    return a;
}

__device__ __forceinline__ void rE_mma(float* d, const uint32_t* a, const uint32_t* b) {
    asm volatile(
        "mma.sync.aligned.m16n8k16.row.col.f32.bf16.bf16.f32 "
        "{%0,%1,%2,%3}, {%4,%5,%6,%7}, {%8,%9}, {%0,%1,%2,%3};\n"
        : "+f"(d[0]), "+f"(d[1]), "+f"(d[2]), "+f"(d[3])
        : "r"(a[0]), "r"(a[1]), "r"(a[2]), "r"(a[3]), "r"(b[0]), "r"(b[1]));
}

#define RE_CPASYNC(dst, src) \
    asm volatile("cp.async.cg.shared.global [%0], [%1], 16;" :: "r"(dst), "l"(src))
#define RE_CPCOMMIT() asm volatile("cp.async.commit_group;" ::: "memory")

// ---------------- fp32 -> bf16 hi/lo split ----------------
__global__ void __launch_bounds__(256) rE_split(const float* __restrict__ src,
                                                __nv_bfloat16* __restrict__ h,
                                                __nv_bfloat16* __restrict__ l,
                                                int n) {
    int i = blockIdx.x * blockDim.x + threadIdx.x;
    if (i >= n) return;
    float a = src[i];
    __nv_bfloat16 hh = __float2bfloat16(a);
    h[i] = hh;
    l[i] = __float2bfloat16(a - __bfloat162float(hh));
}

// ---------------- HMMA split-bf16 GEMM NT, cp.async double-buffered --------
// C[M,N] = (Ah+Al)(Bh+Bl)^T (Al*Bl dropped). Optional fp32 C and bf16 Ch/Cl.
// 256 thr = 8 warps (2Mx4N); warp tile 64x32; BK=32; 2-stage pipeline.
#define RE_STRIDE 40            // bf16 per smem row (32+8 pad): conflict-free
#define RE_ARR   10240          // bytes per array tile (128*40*2)
#define RE_STAGE 40960          // bytes per stage (4 arrays)
extern __shared__ char rE_dsm[];

__device__ __forceinline__ void rE_load_stage(
    uint32_t sbase, const __nv_bfloat16* Ah, const __nv_bfloat16* Al,
    const __nv_bfloat16* Bh, const __nv_bfloat16* Bl,
    int m0, int n0, int K, int k0, int t) {
#pragma unroll
    for (int i = 0; i < 2; i++) {
        int idx = t + (i << 8);
        int r   = idx >> 2;
        int c8  = (idx & 3) * 8;
        uint32_t so = sbase + (uint32_t)(r * RE_STRIDE + c8) * 2;
        size_t ga = (size_t)(m0 + r) * K + k0 + c8;
        size_t gb = (size_t)(n0 + r) * K + k0 + c8;
        RE_CPASYNC(so,              Ah + ga);
        RE_CPASYNC(so + RE_ARR,     Al + ga);
        RE_CPASYNC(so + 2 * RE_ARR, Bh + gb);
        RE_CPASYNC(so + 3 * RE_ARR, Bl + gb);
    }
}

__global__ void __launch_bounds__(256) rE_gemm(
    const __nv_bfloat16* __restrict__ Ah, const __nv_bfloat16* __restrict__ Al,
    const __nv_bfloat16* __restrict__ Bh, const __nv_bfloat16* __restrict__ Bl,
    float* __restrict__ C, __nv_bfloat16* __restrict__ Ch,
    __nv_bfloat16* __restrict__ Cl, int M, int N, int K) {
    const int t    = threadIdx.x;
    const int lane = t & 31;
    const int w    = t >> 5;
    const int wm   = w >> 2;
    const int wn   = w & 3;
    const int m0   = blockIdx.y * 128;
    const int n0   = blockIdx.x * 128;
    const int lr   = lane >> 2;
    const int lc   = (lane & 3) * 2;

    uint32_t sb = rE_smem_u32(rE_dsm);

    float acc[4][4][4];
#pragma unroll
    for (int i = 0; i < 4; i++)
#pragma unroll
        for (int j = 0; j < 4; j++)
#pragma unroll
            for (int k = 0; k < 4; k++) acc[i][j][k] = 0.f;

    const int ns = K >> 5;
    rE_load_stage(sb, Ah, Al, Bh, Bl, m0, n0, K, 0, t);
    RE_CPCOMMIT();

    for (int s = 0; s < ns; s++) {
        if (s + 1 < ns) {
            rE_load_stage(sb + ((s + 1) & 1) * RE_STAGE, Ah, Al, Bh, Bl,
                          m0, n0, K, (s + 1) << 5, t);
            RE_CPCOMMIT();
            asm volatile("cp.async.wait_group 1;" ::: "memory");
        } else {
            asm volatile("cp.async.wait_group 0;" ::: "memory");
        }
        __syncthreads();

        const char* stp = rE_dsm + (s & 1) * RE_STAGE;
        const __nv_bfloat16* sAh = (const __nv_bfloat16*)stp;
        const __nv_bfloat16* sAl = (const __nv_bfloat16*)(stp + RE_ARR);
        const __nv_bfloat16* sBh = (const __nv_bfloat16*)(stp + 2 * RE_ARR);
        const __nv_bfloat16* sBl = (const __nv_bfloat16*)(stp + 3 * RE_ARR);

#pragma unroll
        for (int ks = 0; ks < 2; ks++) {
            const int kk = ks * 16 + lc;
            uint32_t ah[4][4], al[4][4], bh[4][2], bl[4][2];
#pragma unroll
            for (int mt = 0; mt < 4; mt++) {
                int r = wm * 64 + mt * 16 + lr;
                ah[mt][0] = *(const uint32_t*)&sAh[r * RE_STRIDE + kk];
                ah[mt][1] = *(const uint32_t*)&sAh[(r + 8) * RE_STRIDE + kk];
                ah[mt][2] = *(const uint32_t*)&sAh[r * RE_STRIDE + kk + 8];
                ah[mt][3] = *(const uint32_t*)&sAh[(r + 8) * RE_STRIDE + kk + 8];
                al[mt][0] = *(const uint32_t*)&sAl[r * RE_STRIDE + kk];
                al[mt][1] = *(const uint32_t*)&sAl[(r + 8) * RE_STRIDE + kk];
                al[mt][2] = *(const uint32_t*)&sAl[r * RE_STRIDE + kk + 8];
                al[mt][3] = *(const uint32_t*)&sAl[(r + 8) * RE_STRIDE + kk + 8];
            }
#pragma unroll
            for (int nt = 0; nt < 4; nt++) {
                int r = wn * 32 + nt * 8 + lr;
                bh[nt][0] = *(const uint32_t*)&sBh[r * RE_STRIDE + kk];
                bh[nt][1] = *(const uint32_t*)&sBh[r * RE_STRIDE + kk + 8];
                bl[nt][0] = *(const uint32_t*)&sBl[r * RE_STRIDE + kk];
                bl[nt][1] = *(const uint32_t*)&sBl[r * RE_STRIDE + kk + 8];
            }
#pragma unroll
            for (int mt = 0; mt < 4; mt++)
#pragma unroll
                for (int nt = 0; nt < 4; nt++) {
                    rE_mma(acc[mt][nt], ah[mt], bh[nt]);
                    rE_mma(acc[mt][nt], ah[mt], bl[nt]);
                    rE_mma(acc[mt][nt], al[mt], bh[nt]);
                }
        }
        __syncthreads();
    }

    // epilogue: fp32 and/or bf16 hi/lo
#pragma unroll
    for (int mt = 0; mt < 4; mt++) {
#pragma unroll
        for (int nt = 0; nt < 4; nt++) {
#pragma unroll
            for (int half = 0; half < 2; half++) {
                int row = m0 + wm * 64 + mt * 16 + lr + half * 8;
                int col = n0 + wn * 32 + nt * 8 + lc;
                float v0 = acc[mt][nt][half * 2];
                float v1 = acc[mt][nt][half * 2 + 1];
                size_t o = (size_t)row * N + col;
                if (C) { C[o] = v0; C[o + 1] = v1; }
                if (Ch) {
                    __nv_bfloat16 h0 = __float2bfloat16(v0);
                    __nv_bfloat16 h1 = __float2bfloat16(v1);
                    Ch[o] = h0; Ch[o + 1] = h1;
                    Cl[o]     = __float2bfloat16(v0 - __bfloat162float(h0));
                    Cl[o + 1] = __float2bfloat16(v1 - __bfloat162float(h1));
                }
            }
        }
    }
}

// ---------------- rope tables (fast: no double sincos) ----------------
__global__ void __launch_bounds__(256) rE_tables() {
    int idx = blockIdx.x * blockDim.x + threadIdx.x;
    if (idx >= Sc * 32) return;
    int s = idx >> 5;
    int j = idx & 31;
    // invf = 1e5^(-2j/64) = 2^(-j * log2(1e5)/32)
    double invf = exp2((double)(-j) * 0.5190512648261504);
    float ang = (float)s * (float)invf;
    // exact double range reduction, then fast f32 trig
    double angd = (double)ang;
    double k = rint(angd * 0.15915494309189535);   // 1/(2pi)
    float red = (float)(angd - k * 6.283185307179586);
    float c, sn;
    sincosf(red, &c, &sn);
    rE_cos[idx] = c;
    rE_sin[idx] = sn;
}

// ---------------- rope apply once (neg-sin convention, measured) ----------
__global__ void __launch_bounds__(512) rE_rope() {
    int row = blockIdx.x;
    int s   = row & (Sc - 1);
    int t   = threadIdx.x;
    int h   = t >> 5;
    int j   = t & 31;
    float c  = rE_cos[s * 32 + j];
    float sn = rE_sin[s * 32 + j];

    float* qp = rE_q + (size_t)row * Dc + h * HDc + j;
    float a = qp[0], b2 = qp[32];
    qp[0]  = a * c + b2 * sn;
    qp[32] = b2 * c - a * sn;

    float* kp = rE_kv + (size_t)row * (2 * Dc) + h * HDc + j;
    a = kp[0]; b2 = kp[32];
    kp[0]  = a * c + b2 * sn;
    kp[32] = b2 * c - a * sn;
}

// ---------------- block scorer ----------------
__global__ void __launch_bounds__(256) rE_scorer(const float* __restrict__ x,
                                                 const float* __restrict__ w_scorer) {
    int bj = blockIdx.x;
    int b = bj >> 5, j = bj & 31;
    const float* base = x + (size_t)(b * Sc + j * 64) * Dc;
    float sum = 0.f;
    for (int i = threadIdx.x; i < 64 * Dc; i += 256)
        sum += base[i] * w_scorer[i & (Dc - 1)];
    __shared__ float red[256];
    red[threadIdx.x] = sum;
    __syncthreads();
    for (int off = 128; off; off >>= 1) {
        if (threadIdx.x < off) red[threadIdx.x] += red[threadIdx.x + off];
        __syncthreads();
    }
    if (threadIdx.x == 0) rE_scores[bj] = red[0] * (1.0f / 64.0f);
}

// ---------------- top-k ----------------
__global__ void rE_topk() {
    int b = threadIdx.x;
    if (b >= Bc) return;
    float sc[NBc];
    bool used[NBc];
    for (int i = 0; i < NBc; i++) { sc[i] = rE_scores[b * NBc + i]; used[i] = false; }
    int chosen[TOPKc];
    for (int t = 0; t < TOPKc; t++) {
        int best = -1; float bv = -INFINITY;
        for (int i = 0; i < NBc; i++)
            if (!used[i] && sc[i] > bv) { bv = sc[i]; best = i; }
        used[best] = true;
        chosen[t] = best;
    }
    for (int i = 0; i < TOPKc; i++)
        for (int jj = i + 1; jj < TOPKc; jj++)
            if (chosen[jj] < chosen[i]) { int tmp = chosen[i]; chosen[i] = chosen[jj]; chosen[jj] = tmp; }
    for (int i = 0; i < TOPKc; i++) rE_sel[b * TOPKc + i] = chosen[i];
}

// ---------------- v mean over S ----------------
__global__ void __launch_bounds__(256) rE_vmeank() {
    int idx = blockIdx.x * blockDim.x + threadIdx.x;
    if (idx >= Bc * Dc) return;
    int b = idx >> 10, d = idx & (Dc - 1);
    const float* base = rE_kv + (size_t)b * Sc * (2 * Dc) + Dc + d;
    float sum = 0.f;
#pragma unroll 8
    for (int s = 0; s < Sc; s++) sum += base[(size_t)s * (2 * Dc)];
    rE_vmean[idx] = sum * (1.0f / (float)Sc);
}

// ---------------- tiled flash attention, writes bf16 hi/lo directly --------
__global__ void __launch_bounds__(256) rE_attn() {
    extern __shared__ float sm[];
    float* Qs = sm;
    float* KV = sm + 64 * 68;
    float* Ps = sm + 2 * 64 * 68;

    int lin = blockIdx.x;
    int qt = lin & 31;
    int h  = (lin >> 5) & (Hc - 1);
    int b  = lin >> 9;
    int t  = threadIdx.x;
    int ty = t >> 4, tx = t & 15;
    int r0 = ty << 2, c0 = tx << 2;

    __shared__ int sel_s[TOPKc];
    if (t < TOPKc) sel_s[t] = rE_sel[b * TOPKc + t];
    __syncthreads();
    int min_sel = sel_s[0];

    if (qt < min_sel) {
        float4 vm = *(const float4*)&rE_vmean[b * Dc + h * HDc + c0];
        float vv[4] = {vm.x, vm.y, vm.z, vm.w};
#pragma unroll
        for (int i = 0; i < 4; i++) {
            size_t o = (size_t)(b * Sc + qt * 64 + r0 + i) * Dc + h * HDc + c0;
#pragma unroll
            for (int j = 0; j < 4; j++) {
                __nv_bfloat16 hh = __float2bfloat16(vv[j]);
                rE_aoh[o + j] = hh;
                rE_aol[o + j] = __float2bfloat16(vv[j] - __bfloat162float(hh));
            }
        }
        return;
    }

    const float* qg = rE_q + (size_t)(b * Sc + qt * 64) * Dc + h * HDc;
#pragma unroll
    for (int rr = 0; rr < 4; rr++) {
        int slot = t + 256 * rr;
        int row  = slot >> 4;
        int cc   = (slot & 15) << 2;
        *(float4*)&Qs[row * 68 + cc] = *(const float4*)(qg + (size_t)row * Dc + cc);
    }

    float m[4], l[4], o[4][4];
#pragma unroll
    for (int i = 0; i < 4; i++) {
        m[i] = -INFINITY; l[i] = 0.f;
#pragma unroll
        for (int j = 0; j < 4; j++) o[i][j] = 0.f;
    }

    for (int ib = 0; ib < TOPKc; ib++) {
        int kb = sel_s[ib];
        if (kb > qt) break;
        const float* kg = rE_kv + (size_t)(b * Sc + kb * 64) * (2 * Dc) + h * HDc;

        __syncthreads();
#pragma unroll
        for (int rr = 0; rr < 4; rr++) {
            int slot = t + 256 * rr;
            int row  = slot >> 4;
            int cc   = (slot & 15) << 2;
            float4 v = *(const float4*)(kg + (size_t)row * (2 * Dc) + cc);
            KV[(cc + 0) * 68 + row] = v.x;
            KV[(cc + 1) * 68 + row] = v.y;
            KV[(cc + 2) * 68 + row] = v.z;
            KV[(cc + 3) * 68 + row] = v.w;
        }
        __syncthreads();

        float s[4][4];
#pragma unroll
        for (int i = 0; i < 4; i++)
#pragma unroll
            for (int j = 0; j < 4; j++) s[i][j] = 0.f;
#pragma unroll 16
        for (int d = 0; d < 64; d++) {
            float4 k4 = *(const float4*)&KV[d * 68 + c0];
            float q0 = Qs[(r0 + 0) * 68 + d];
            float q1 = Qs[(r0 + 1) * 68 + d];
            float q2 = Qs[(r0 + 2) * 68 + d];
            float q3 = Qs[(r0 + 3) * 68 + d];
            s[0][0] += q0 * k4.x; s[0][1] += q0 * k4.y; s[0][2] += q0 * k4.z; s[0][3] += q0 * k4.w;
            s[1][0] += q1 * k4.x; s[1][1] += q1 * k4.y; s[1][2] += q1 * k4.z; s[1][3] += q1 * k4.w;
            s[2][0] += q2 * k4.x; s[2][1] += q2 * k4.y; s[2][2] += q2 * k4.z; s[2][3] += q2 * k4.w;
            s[3][0] += q3 * k4.x; s[3][1] += q3 * k4.y; s[3][2] += q3 * k4.z; s[3][3] += q3 * k4.w;
        }
        bool diag = (kb == qt);
#pragma unroll
        for (int i = 0; i < 4; i++)
#pragma unroll
            for (int j = 0; j < 4; j++) {
                s[i][j] *= 0.125f;
                if (diag && (c0 + j) > (r0 + i)) s[i][j] = -INFINITY;
            }

#pragma unroll
        for (int i = 0; i < 4; i++) {
            float v = fmaxf(fmaxf(s[i][0], s[i][1]), fmaxf(s[i][2], s[i][3]));
#pragma unroll
            for (int off = 8; off; off >>= 1)
                v = fmaxf(v, __shfl_xor_sync(0xffffffffu, v, off, 16));
            float mnew = fmaxf(m[i], v);
            float alpha = expf(m[i] - mnew);
            float p0 = expf(s[i][0] - mnew);
            float p1 = expf(s[i][1] - mnew);
            float p2 = expf(s[i][2] - mnew);
            float p3 = expf(s[i][3] - mnew);
            float rv = p0 + p1 + p2 + p3;
#pragma unroll
            for (int off = 8; off; off >>= 1)
                rv += __shfl_xor_sync(0xffffffffu, rv, off, 16);
            l[i] = l[i] * alpha + rv;
            m[i] = mnew;
            o[i][0] *= alpha; o[i][1] *= alpha; o[i][2] *= alpha; o[i][3] *= alpha;
            *(float4*)&Ps[(r0 + i) * 68 + c0] = make_float4(p0, p1, p2, p3);
        }
        __syncthreads();

#pragma unroll
        for (int rr = 0; rr < 4; rr++) {
            int slot = t + 256 * rr;
            int row  = slot >> 4;
            int cc   = (slot & 15) << 2;
            *(float4*)&KV[row * 68 + cc] =
                *(const float4*)(kg + Dc + (size_t)row * (2 * Dc) + cc);
        }
        __syncthreads();

#pragma unroll 16
        for (int k = 0; k < 64; k++) {
            float4 v4 = *(const float4*)&KV[k * 68 + c0];
            float p0 = Ps[(r0 + 0) * 68 + k];
            float p1 = Ps[(r0 + 1) * 68 + k];
            float p2 = Ps[(r0 + 2) * 68 + k];
            float p3 = Ps[(r0 + 3) * 68 + k];
            o[0][0] += p0 * v4.x; o[0][1] += p0 * v4.y; o[0][2] += p0 * v4.z; o[0][3] += p0 * v4.w;
            o[1][0] += p1 * v4.x; o[1][1] += p1 * v4.y; o[1][2] += p1 * v4.z; o[1][3] += p1 * v4.w;
            o[2][0] += p2 * v4.x; o[2][1] += p2 * v4.y; o[2][2] += p2 * v4.z; o[2][3] += p2 * v4.w;
            o[3][0] += p3 * v4.x; o[3][1] += p3 * v4.y; o[3][2] += p3 * v4.z; o[3][3] += p3 * v4.w;
        }
    }

#pragma unroll
    for (int i = 0; i < 4; i++) {
        float inv = 1.0f / l[i];
        size_t ob = (size_t)(b * Sc + qt * 64 + r0 + i) * Dc + h * HDc + c0;
#pragma unroll
        for (int j = 0; j < 4; j++) {
            float val = o[i][j] * inv;
            __nv_bfloat16 hh = __float2bfloat16(val);
            rE_aoh[ob + j] = hh;
            rE_aol[ob + j] = __float2bfloat16(val - __bfloat162float(hh));
        }
    }
}

// ---------------- launch ----------------
extern "C" void kernel_launch(void* const* d_in, const int* in_sizes, int n_in,
                              void* d_out, int out_size) {
    const float* x         = (const float*)d_in[0];
    const float* w_q       = (const float*)d_in[1];
    const float* w_kv_down = (const float*)d_in[2];
    const float* w_kv_up   = (const float*)d_in[3];
    const float* w_out     = (const float*)d_in[4];
    const float* w_scorer  = (const float*)d_in[5];
    float* out = (float*)d_out;

    float *q, *kv;
    cudaGetSymbolAddress((void**)&q,  rE_q);
    cudaGetSymbolAddress((void**)&kv, rE_kv);
    __nv_bfloat16 *xh, *xl, *wqh, *wql, *wkdh, *wkdl, *wkuh, *wkul, *woh, *wol,
                  *lath, *latl, *aoh, *aol;
    cudaGetSymbolAddress((void**)&xh,   rE_xh);   cudaGetSymbolAddress((void**)&xl,   rE_xl);
    cudaGetSymbolAddress((void**)&wqh,  rE_wqh);  cudaGetSymbolAddress((void**)&wql,  rE_wql);
    cudaGetSymbolAddress((void**)&wkdh, rE_wkdh); cudaGetSymbolAddress((void**)&wkdl, rE_wkdl);
    cudaGetSymbolAddress((void**)&wkuh, rE_wkuh); cudaGetSymbolAddress((void**)&wkul, rE_wkul);
    cudaGetSymbolAddress((void**)&woh,  rE_woh);  cudaGetSymbolAddress((void**)&wol,  rE_wol);
    cudaGetSymbolAddress((void**)&lath, rE_lath); cudaGetSymbolAddress((void**)&latl, rE_latl);
    cudaGetSymbolAddress((void**)&aoh,  rE_aoh);  cudaGetSymbolAddress((void**)&aol,  rE_aol);

    const int M = Bc * Sc;  // 4096
    const int GSMEM = 2 * RE_STAGE;  // 81920
    cudaFuncSetAttribute(rE_gemm, cudaFuncAttributeMaxDynamicSharedMemorySize, GSMEM);

    auto nb = [](int n) { return (n + 255) / 256; };

    // splits of inputs
    rE_split<<<nb(M * Dc), 256>>>(x, xh, xl, M * Dc);
    rE_split<<<nb(Dc * Dc), 256>>>(w_q, wqh, wql, Dc * Dc);
    rE_split<<<nb(Rc * Dc), 256>>>(w_kv_down, wkdh, wkdl, Rc * Dc);
    rE_split<<<nb(2 * Dc * Rc), 256>>>(w_kv_up, wkul ? wkuh : wkuh, wkul, 2 * Dc * Rc);
    rE_split<<<nb(Dc * Dc), 256>>>(w_out, woh, wol, Dc * Dc);

    // q = x @ w_q^T (fp32 out, needs rope)
    rE_gemm<<<dim3(Dc / 128, M / 128), 256, GSMEM>>>(xh, xl, wqh, wql, q, nullptr, nullptr, M, Dc, Dc);
    // lat = x @ w_kv_down^T (bf16 hi/lo out only)
    rE_gemm<<<dim3(Rc / 128, M / 128), 256, GSMEM>>>(xh, xl, wkdh, wkdl, nullptr, lath, latl, M, Rc, Dc);
    // kv = lat @ w_kv_up^T (fp32 out)
    rE_gemm<<<dim3((2 * Dc) / 128, M / 128), 256, GSMEM>>>(lath, latl, wkuh, wkul, kv, nullptr, nullptr, M, 2 * Dc, Rc);

    rE_tables<<<(Sc * 32 + 255) / 256, 256>>>();
    rE_rope<<<M, 512>>>();
    rE_scorer<<<Bc * NBc, 256>>>(x, w_scorer);
    rE_topk<<<1, 32>>>();
    rE_vmeank<<<(Bc * Dc + 255) / 256, 256>>>();

    int smem = 3 * 64 * 68 * sizeof(float);
    cudaFuncSetAttribute(rE_attn, cudaFuncAttributeMaxDynamicSharedMemorySize, smem);
    rE_attn<<<Bc * Hc * (Sc / 64), 256, smem>>>();

    // out = attn @ w_out^T
    rE_gemm<<<dim3(Dc / 128, M / 128), 256, GSMEM>>>(aoh, aol, woh, wol, out, nullptr, nullptr, M, Dc, Dc);
}

// round 16
// speedup vs baseline: 1.3533x; 1.3533x over previous
#include <cuda_runtime.h>
#include <cuda_bf16.h>
#include <math.h>
#include <stdint.h>

#define Bc 2
#define Sc 2048
#define Dc 1024
#define Hc 16
#define HDc 64
#define Rc 128
#define NBc 32
#define TOPKc 4

// ---------------- scratch (no device allocs) ----------------
__device__ float rF_q[Bc*Sc*Dc];
__device__ float rF_kv[Bc*Sc*2*Dc];
__device__ float rF_scores[Bc*NBc];
__device__ int   rF_sel[Bc*TOPKc];
__device__ float rF_vmean[Bc*Dc];
__device__ float rF_cos[Sc*32];
__device__ float rF_sin[Sc*32];
// bf16 hi/lo splits
__device__ __nv_bfloat16 rF_xh[Bc*Sc*Dc],   rF_xl[Bc*Sc*Dc];
__device__ __nv_bfloat16 rF_wqh[Dc*Dc],     rF_wql[Dc*Dc];
__device__ __nv_bfloat16 rF_wkdh[Rc*Dc],    rF_wkdl[Rc*Dc];
__device__ __nv_bfloat16 rF_wkuh[2*Dc*Rc],  rF_wkul[2*Dc*Rc];
__device__ __nv_bfloat16 rF_woh[Dc*Dc],     rF_wol[Dc*Dc];
__device__ __nv_bfloat16 rF_lath[Bc*Sc*Rc], rF_latl[Bc*Sc*Rc];
__device__ __nv_bfloat16 rF_aoh[Bc*Sc*Dc],  rF_aol[Bc*Sc*Dc];

// ---------------- fp32 -> bf16 hi/lo split ----------------
__global__ void __launch_bounds__(256) rF_split(const float* __restrict__ src,
                                                __nv_bfloat16* __restrict__ h,
                                                __nv_bfloat16* __restrict__ l,
                                                int n) {
    int i = blockIdx.x * blockDim.x + threadIdx.x;
    if (i >= n) return;
    float a = src[i];
    __nv_bfloat16 hh = __float2bfloat16(a);
    h[i] = hh;
    l[i] = __float2bfloat16(a - __bfloat162float(hh));
}

// ---------------- mma.sync helper ----------------
__device__ __forceinline__ void rF_mma(float* d, const uint32_t* a, const uint32_t* b) {
    asm volatile(
        "mma.sync.aligned.m16n8k16.row.col.f32.bf16.bf16.f32 "
        "{%0,%1,%2,%3}, {%4,%5,%6,%7}, {%8,%9}, {%0,%1,%2,%3};\n"
        : "+f"(d[0]), "+f"(d[1]), "+f"(d[2]), "+f"(d[3])
        : "r"(a[0]), "r"(a[1]), "r"(a[2]), "r"(a[3]), "r"(b[0]), "r"(b[1]));
}

// ---------------- HMMA split-bf16 GEMM NT (proven R14 structure) -----------
// C[M,N] = (Ah+Al)(Bh+Bl)^T (Al*Bl dropped). Optional fp32 C and bf16 Ch/Cl.
#define RF_STRIDE 40   // bf16 per smem row (32 + 8 pad) -> conflict-free
__global__ void __launch_bounds__(256) rF_gemm(
    const __nv_bfloat16* __restrict__ Ah, const __nv_bfloat16* __restrict__ Al,
    const __nv_bfloat16* __restrict__ Bh, const __nv_bfloat16* __restrict__ Bl,
    float* __restrict__ C, __nv_bfloat16* __restrict__ Ch,
    __nv_bfloat16* __restrict__ Cl, int M, int N, int K) {
    __shared__ __nv_bfloat16 sAh[128 * RF_STRIDE], sAl[128 * RF_STRIDE];
    __shared__ __nv_bfloat16 sBh[128 * RF_STRIDE], sBl[128 * RF_STRIDE];

    const int t    = threadIdx.x;
    const int lane = t & 31;
    const int w    = t >> 5;
    const int wm   = w >> 2;
    const int wn   = w & 3;
    const int m0   = blockIdx.y * 128;
    const int n0   = blockIdx.x * 128;
    const int lr   = lane >> 2;
    const int lc   = (lane & 3) * 2;

    float acc[4][4][4];
#pragma unroll
    for (int i = 0; i < 4; i++)
#pragma unroll
        for (int j = 0; j < 4; j++)
#pragma unroll
            for (int k = 0; k < 4; k++) acc[i][j][k] = 0.f;

    for (int k0 = 0; k0 < K; k0 += 32) {
#pragma unroll
        for (int i = 0; i < 2; i++) {
            int idx = t + i * 256;
            int r   = idx >> 2;
            int c8  = (idx & 3) * 8;
            size_t ga = (size_t)(m0 + r) * K + k0 + c8;
            size_t gb = (size_t)(n0 + r) * K + k0 + c8;
            *(uint4*)&sAh[r * RF_STRIDE + c8] = *(const uint4*)&Ah[ga];
            *(uint4*)&sAl[r * RF_STRIDE + c8] = *(const uint4*)&Al[ga];
            *(uint4*)&sBh[r * RF_STRIDE + c8] = *(const uint4*)&Bh[gb];
            *(uint4*)&sBl[r * RF_STRIDE + c8] = *(const uint4*)&Bl[gb];
        }
        __syncthreads();

#pragma unroll
        for (int ks = 0; ks < 2; ks++) {
            const int kk = ks * 16 + lc;
            uint32_t ah[4][4], al[4][4], bh[4][2], bl[4][2];
#pragma unroll
            for (int mt = 0; mt < 4; mt++) {
                int r = wm * 64 + mt * 16 + lr;
                ah[mt][0] = *(const uint32_t*)&sAh[r * RF_STRIDE + kk];
                ah[mt][1] = *(const uint32_t*)&sAh[(r + 8) * RF_STRIDE + kk];
                ah[mt][2] = *(const uint32_t*)&sAh[r * RF_STRIDE + kk + 8];
                ah[mt][3] = *(const uint32_t*)&sAh[(r + 8) * RF_STRIDE + kk + 8];
                al[mt][0] = *(const uint32_t*)&sAl[r * RF_STRIDE + kk];
                al[mt][1] = *(const uint32_t*)&sAl[(r + 8) * RF_STRIDE + kk];
                al[mt][2] = *(const uint32_t*)&sAl[r * RF_STRIDE + kk + 8];
                al[mt][3] = *(const uint32_t*)&sAl[(r + 8) * RF_STRIDE + kk + 8];
            }
#pragma unroll
            for (int nt = 0; nt < 4; nt++) {
                int r = wn * 32 + nt * 8 + lr;
                bh[nt][0] = *(const uint32_t*)&sBh[r * RF_STRIDE + kk];
                bh[nt][1] = *(const uint32_t*)&sBh[r * RF_STRIDE + kk + 8];
                bl[nt][0] = *(const uint32_t*)&sBl[r * RF_STRIDE + kk];
                bl[nt][1] = *(const uint32_t*)&sBl[r * RF_STRIDE + kk + 8];
            }
#pragma unroll
            for (int mt = 0; mt < 4; mt++)
#pragma unroll
                for (int nt = 0; nt < 4; nt++) {
                    rF_mma(acc[mt][nt], ah[mt], bh[nt]);
                    rF_mma(acc[mt][nt], ah[mt], bl[nt]);
                    rF_mma(acc[mt][nt], al[mt], bh[nt]);
                }
        }
        __syncthreads();
    }

    // epilogue: fp32 and/or bf16 hi/lo
#pragma unroll
    for (int mt = 0; mt < 4; mt++) {
#pragma unroll
        for (int nt = 0; nt < 4; nt++) {
#pragma unroll
            for (int half = 0; half < 2; half++) {
                int row = m0 + wm * 64 + mt * 16 + lr + half * 8;
                int col = n0 + wn * 32 + nt * 8 + lc;
                float v0 = acc[mt][nt][half * 2];
                float v1 = acc[mt][nt][half * 2 + 1];
                size_t o = (size_t)row * N + col;
                if (C) { C[o] = v0; C[o + 1] = v1; }
                if (Ch) {
                    __nv_bfloat16 h0 = __float2bfloat16(v0);
                    __nv_bfloat16 h1 = __float2bfloat16(v1);
                    Ch[o] = h0; Ch[o + 1] = h1;
                    Cl[o]     = __float2bfloat16(v0 - __bfloat162float(h0));
                    Cl[o + 1] = __float2bfloat16(v1 - __bfloat162float(h1));
                }
            }
        }
    }
}

// ---------------- rope tables (fast) ----------------
__global__ void __launch_bounds__(256) rF_tables() {
    int idx = blockIdx.x * blockDim.x + threadIdx.x;
    if (idx >= Sc * 32) return;
    int s = idx >> 5;
    int j = idx & 31;
    double invf = exp2((double)(-j) * 0.5190512648261504);  // 1e5^(-j/32)
    float ang = (float)s * (float)invf;
    double angd = (double)ang;
    double k = rint(angd * 0.15915494309189535);
    float red = (float)(angd - k * 6.283185307179586);
    float c, sn;
    sincosf(red, &c, &sn);
    rF_cos[idx] = c;
    rF_sin[idx] = sn;
}

// ---------------- rope apply once (neg-sin convention, measured) ----------
__global__ void __launch_bounds__(512) rF_rope() {
    int row = blockIdx.x;
    int s   = row & (Sc - 1);
    int t   = threadIdx.x;
    int h   = t >> 5;
    int j   = t & 31;
    float c  = rF_cos[s * 32 + j];
    float sn = rF_sin[s * 32 + j];

    float* qp = rF_q + (size_t)row * Dc + h * HDc + j;
    float a = qp[0], b2 = qp[32];
    qp[0]  = a * c + b2 * sn;
    qp[32] = b2 * c - a * sn;

    float* kp = rF_kv + (size_t)row * (2 * Dc) + h * HDc + j;
    a = kp[0]; b2 = kp[32];
    kp[0]  = a * c + b2 * sn;
    kp[32] = b2 * c - a * sn;
}

// ---------------- block scorer ----------------
__global__ void __launch_bounds__(256) rF_scorer(const float* __restrict__ x,
                                                 const float* __restrict__ w_scorer) {
    int bj = blockIdx.x;
    int b = bj >> 5, j = bj & 31;
    const float* base = x + (size_t)(b * Sc + j * 64) * Dc;
    float sum = 0.f;
    for (int i = threadIdx.x; i < 64 * Dc; i += 256)
        sum += base[i] * w_scorer[i & (Dc - 1)];
    __shared__ float red[256];
    red[threadIdx.x] = sum;
    __syncthreads();
    for (int off = 128; off; off >>= 1) {
        if (threadIdx.x < off) red[threadIdx.x] += red[threadIdx.x + off];
        __syncthreads();
    }
    if (threadIdx.x == 0) rF_scores[bj] = red[0] * (1.0f / 64.0f);
}

// ---------------- top-k ----------------
__global__ void rF_topk() {
    int b = threadIdx.x;
    if (b >= Bc) return;
    float sc[NBc];
    bool used[NBc];
    for (int i = 0; i < NBc; i++) { sc[i] = rF_scores[b * NBc + i]; used[i] = false; }
    int chosen[TOPKc];
    for (int t = 0; t < TOPKc; t++) {
        int best = -1; float bv = -INFINITY;
        for (int i = 0; i < NBc; i++)
            if (!used[i] && sc[i] > bv) { bv = sc[i]; best = i; }
        used[best] = true;
        chosen[t] = best;
    }
    for (int i = 0; i < TOPKc; i++)
        for (int jj = i + 1; jj < TOPKc; jj++)
            if (chosen[jj] < chosen[i]) { int tmp = chosen[i]; chosen[i] = chosen[jj]; chosen[jj] = tmp; }
    for (int i = 0; i < TOPKc; i++) rF_sel[b * TOPKc + i] = chosen[i];
}

// ---------------- v mean over S ----------------
__global__ void __launch_bounds__(256) rF_vmeank() {
    int idx = blockIdx.x * blockDim.x + threadIdx.x;
    if (idx >= Bc * Dc) return;
    int b = idx >> 10, d = idx & (Dc - 1);
    const float* base = rF_kv + (size_t)b * Sc * (2 * Dc) + Dc + d;
    float sum = 0.f;
#pragma unroll 8
    for (int s = 0; s < Sc; s++) sum += base[(size_t)s * (2 * Dc)];
    rF_vmean[idx] = sum * (1.0f / (float)Sc);
}

// ---------------- tiled flash attention, writes bf16 hi/lo directly --------
__global__ void __launch_bounds__(256) rF_attn() {
    extern __shared__ float sm[];
    float* Qs = sm;
    float* KV = sm + 64 * 68;
    float* Ps = sm + 2 * 64 * 68;

    int lin = blockIdx.x;
    int qt = lin & 31;
    int h  = (lin >> 5) & (Hc - 1);
    int b  = lin >> 9;
    int t  = threadIdx.x;
    int ty = t >> 4, tx = t & 15;
    int r0 = ty << 2, c0 = tx << 2;

    __shared__ int sel_s[TOPKc];
    if (t < TOPKc) sel_s[t] = rF_sel[b * TOPKc + t];
    __syncthreads();
    int min_sel = sel_s[0];

    if (qt < min_sel) {
        float4 vm = *(const float4*)&rF_vmean[b * Dc + h * HDc + c0];
        float vv[4] = {vm.x, vm.y, vm.z, vm.w};
#pragma unroll
        for (int i = 0; i < 4; i++) {
            size_t o = (size_t)(b * Sc + qt * 64 + r0 + i) * Dc + h * HDc + c0;
#pragma unroll
            for (int j = 0; j < 4; j++) {
                __nv_bfloat16 hh = __float2bfloat16(vv[j]);
                rF_aoh[o + j] = hh;
                rF_aol[o + j] = __float2bfloat16(vv[j] - __bfloat162float(hh));
            }
        }
        return;
    }

    const float* qg = rF_q + (size_t)(b * Sc + qt * 64) * Dc + h * HDc;
#pragma unroll
    for (int rr = 0; rr < 4; rr++) {
        int slot = t + 256 * rr;
        int row  = slot >> 4;
        int cc   = (slot & 15) << 2;
        *(float4*)&Qs[row * 68 + cc] = *(const float4*)(qg + (size_t)row * Dc + cc);
    }

    float m[4], l[4], o[4][4];
#pragma unroll
    for (int i = 0; i < 4; i++) {
        m[i] = -INFINITY; l[i] = 0.f;
#pragma unroll
        for (int j = 0; j < 4; j++) o[i][j] = 0.f;
    }

    for (int ib = 0; ib < TOPKc; ib++) {
        int kb = sel_s[ib];
        if (kb > qt) break;
        const float* kg = rF_kv + (size_t)(b * Sc + kb * 64) * (2 * Dc) + h * HDc;

        __syncthreads();
#pragma unroll
        for (int rr = 0; rr < 4; rr++) {
            int slot = t + 256 * rr;
            int row  = slot >> 4;
            int cc   = (slot & 15) << 2;
            float4 v = *(const float4*)(kg + (size_t)row * (2 * Dc) + cc);
            KV[(cc + 0) * 68 + row] = v.x;
            KV[(cc + 1) * 68 + row] = v.y;
            KV[(cc + 2) * 68 + row] = v.z;
            KV[(cc + 3) * 68 + row] = v.w;
        }
        __syncthreads();

        float s[4][4];
#pragma unroll
        for (int i = 0; i < 4; i++)
#pragma unroll
            for (int j = 0; j < 4; j++) s[i][j] = 0.f;
#pragma unroll 16
        for (int d = 0; d < 64; d++) {
            float4 k4 = *(const float4*)&KV[d * 68 + c0];
            float q0 = Qs[(r0 + 0) * 68 + d];
            float q1 = Qs[(r0 + 1) * 68 + d];
            float q2 = Qs[(r0 + 2) * 68 + d];
            float q3 = Qs[(r0 + 3) * 68 + d];
            s[0][0] += q0 * k4.x; s[0][1] += q0 * k4.y; s[0][2] += q0 * k4.z; s[0][3] += q0 * k4.w;
            s[1][0] += q1 * k4.x; s[1][1] += q1 * k4.y; s[1][2] += q1 * k4.z; s[1][3] += q1 * k4.w;
            s[2][0] += q2 * k4.x; s[2][1] += q2 * k4.y; s[2][2] += q2 * k4.z; s[2][3] += q2 * k4.w;
            s[3][0] += q3 * k4.x; s[3][1] += q3 * k4.y; s[3][2] += q3 * k4.z; s[3][3] += q3 * k4.w;
        }
        bool diag = (kb == qt);
#pragma unroll
        for (int i = 0; i < 4; i++)
#pragma unroll
            for (int j = 0; j < 4; j++) {
                s[i][j] *= 0.125f;
                if (diag && (c0 + j) > (r0 + i)) s[i][j] = -INFINITY;
            }

#pragma unroll
        for (int i = 0; i < 4; i++) {
            float v = fmaxf(fmaxf(s[i][0], s[i][1]), fmaxf(s[i][2], s[i][3]));
#pragma unroll
            for (int off = 8; off; off >>= 1)
                v = fmaxf(v, __shfl_xor_sync(0xffffffffu, v, off, 16));
            float mnew = fmaxf(m[i], v);
            float alpha = expf(m[i] - mnew);
            float p0 = expf(s[i][0] - mnew);
            float p1 = expf(s[i][1] - mnew);
            float p2 = expf(s[i][2] - mnew);
            float p3 = expf(s[i][3] - mnew);
            float rv = p0 + p1 + p2 + p3;
#pragma unroll
            for (int off = 8; off; off >>= 1)
                rv += __shfl_xor_sync(0xffffffffu, rv, off, 16);
            l[i] = l[i] * alpha + rv;
            m[i] = mnew;
            o[i][0] *= alpha; o[i][1] *= alpha; o[i][2] *= alpha; o[i][3] *= alpha;
            *(float4*)&Ps[(r0 + i) * 68 + c0] = make_float4(p0, p1, p2, p3);
        }
        __syncthreads();

#pragma unroll
        for (int rr = 0; rr < 4; rr++) {
            int slot = t + 256 * rr;
            int row  = slot >> 4;
            int cc   = (slot & 15) << 2;
            *(float4*)&KV[row * 68 + cc] =
                *(const float4*)(kg + Dc + (size_t)row * (2 * Dc) + cc);
        }
        __syncthreads();

#pragma unroll 16
        for (int k = 0; k < 64; k++) {
            float4 v4 = *(const float4*)&KV[k * 68 + c0];
            float p0 = Ps[(r0 + 0) * 68 + k];
            float p1 = Ps[(r0 + 1) * 68 + k];
            float p2 = Ps[(r0 + 2) * 68 + k];
            float p3 = Ps[(r0 + 3) * 68 + k];
            o[0][0] += p0 * v4.x; o[0][1] += p0 * v4.y; o[0][2] += p0 * v4.z; o[0][3] += p0 * v4.w;
            o[1][0] += p1 * v4.x; o[1][1] += p1 * v4.y; o[1][2] += p1 * v4.z; o[1][3] += p1 * v4.w;
            o[2][0] += p2 * v4.x; o[2][1] += p2 * v4.y; o[2][2] += p2 * v4.z; o[2][3] += p2 * v4.w;
            o[3][0] += p3 * v4.x; o[3][1] += p3 * v4.y; o[3][2] += p3 * v4.z; o[3][3] += p3 * v4.w;
        }
    }

#pragma unroll
    for (int i = 0; i < 4; i++) {
        float inv = 1.0f / l[i];
        size_t ob = (size_t)(b * Sc + qt * 64 + r0 + i) * Dc + h * HDc + c0;
#pragma unroll
        for (int j = 0; j < 4; j++) {
            float val = o[i][j] * inv;
            __nv_bfloat16 hh = __float2bfloat16(val);
            rF_aoh[ob + j] = hh;
            rF_aol[ob + j] = __float2bfloat16(val - __bfloat162float(hh));
        }
    }
}

// ---------------- launch ----------------
extern "C" void kernel_launch(void* const* d_in, const int* in_sizes, int n_in,
                              void* d_out, int out_size) {
    const float* x         = (const float*)d_in[0];
    const float* w_q       = (const float*)d_in[1];
    const float* w_kv_down = (const float*)d_in[2];
    const float* w_kv_up   = (const float*)d_in[3];
    const float* w_out     = (const float*)d_in[4];
    const float* w_scorer  = (const float*)d_in[5];
    float* out = (float*)d_out;

    float *q, *kv;
    cudaGetSymbolAddress((void**)&q,  rF_q);
    cudaGetSymbolAddress((void**)&kv, rF_kv);
    __nv_bfloat16 *xh, *xl, *wqh, *wql, *wkdh, *wkdl, *wkuh, *wkul, *woh, *wol,
                  *lath, *latl, *aoh, *aol;
    cudaGetSymbolAddress((void**)&xh,   rF_xh);   cudaGetSymbolAddress((void**)&xl,   rF_xl);
    cudaGetSymbolAddress((void**)&wqh,  rF_wqh);  cudaGetSymbolAddress((void**)&wql,  rF_wql);
    cudaGetSymbolAddress((void**)&wkdh, rF_wkdh); cudaGetSymbolAddress((void**)&wkdl, rF_wkdl);
    cudaGetSymbolAddress((void**)&wkuh, rF_wkuh); cudaGetSymbolAddress((void**)&wkul, rF_wkul);
    cudaGetSymbolAddress((void**)&woh,  rF_woh);  cudaGetSymbolAddress((void**)&wol,  rF_wol);
    cudaGetSymbolAddress((void**)&lath, rF_lath); cudaGetSymbolAddress((void**)&latl, rF_latl);
    cudaGetSymbolAddress((void**)&aoh,  rF_aoh);  cudaGetSymbolAddress((void**)&aol,  rF_aol);

    const int M = Bc * Sc;  // 4096
    auto nb = [](int n) { return (n + 255) / 256; };

    // splits of inputs
    rF_split<<<nb(M * Dc), 256>>>(x, xh, xl, M * Dc);
    rF_split<<<nb(Dc * Dc), 256>>>(w_q, wqh, wql, Dc * Dc);
    rF_split<<<nb(Rc * Dc), 256>>>(w_kv_down, wkdh, wkdl, Rc * Dc);
    rF_split<<<nb(2 * Dc * Rc), 256>>>(w_kv_up, wkuh, wkul, 2 * Dc * Rc);
    rF_split<<<nb(Dc * Dc), 256>>>(w_out, woh, wol, Dc * Dc);

    // q = x @ w_q^T (fp32; rope applied after)
    rF_gemm<<<dim3(Dc / 128, M / 128), 256>>>(xh, xl, wqh, wql, q, nullptr, nullptr, M, Dc, Dc);
    // lat = x @ w_kv_down^T (bf16 hi/lo only; no fp32 round-trip)
    rF_gemm<<<dim3(Rc / 128, M / 128), 256>>>(xh, xl, wkdh, wkdl, nullptr, lath, latl, M, Rc, Dc);
    // kv = lat @ w_kv_up^T (fp32)
    rF_gemm<<<dim3((2 * Dc) / 128, M / 128), 256>>>(lath, latl, wkuh, wkul, kv, nullptr, nullptr, M, 2 * Dc, Rc);

    rF_tables<<<(Sc * 32 + 255) / 256, 256>>>();
    rF_rope<<<M, 512>>>();
    rF_scorer<<<Bc * NBc, 256>>>(x, w_scorer);
    rF_topk<<<1, 32>>>();
    rF_vmeank<<<(Bc * Dc + 255) / 256, 256>>>();

    int smem = 3 * 64 * 68 * sizeof(float);
    cudaFuncSetAttribute(rF_attn, cudaFuncAttributeMaxDynamicSharedMemorySize, smem);
    rF_attn<<<Bc * Hc * (Sc / 64), 256, smem>>>();

    // out = attn @ w_out^T
    rF_gemm<<<dim3(Dc / 128, M / 128), 256>>>(aoh, aol, woh, wol, out, nullptr, nullptr, M, Dc, Dc);
}

// round 17
// speedup vs baseline: 1.7157x; 1.2678x over previous
#include <cuda_runtime.h>
#include <cuda_bf16.h>
#include <math.h>
#include <stdint.h>

#define Bc 2
#define Sc 2048
#define Dc 1024
#define Hc 16
#define HDc 64
#define Rc 128
#define NBc 32
#define TOPKc 4

// ---------------- scratch (no device allocs) ----------------
__device__ float rG_q[Bc*Sc*Dc];
__device__ float rG_kv[Bc*Sc*2*Dc];
__device__ float rG_scores[Bc*NBc];
__device__ int   rG_sel[Bc*TOPKc];
__device__ float rG_vmean[Bc*Dc];
__device__ float rG_vpart[8*Bc*Dc];
__device__ float rG_cos[Sc*32];
__device__ float rG_sin[Sc*32];
// bf16 hi/lo splits
__device__ __nv_bfloat16 rG_xh[Bc*Sc*Dc],   rG_xl[Bc*Sc*Dc];
__device__ __nv_bfloat16 rG_wqh[Dc*Dc],     rG_wql[Dc*Dc];
__device__ __nv_bfloat16 rG_wkdh[Rc*Dc],    rG_wkdl[Rc*Dc];
__device__ __nv_bfloat16 rG_wkuh[2*Dc*Rc],  rG_wkul[2*Dc*Rc];
__device__ __nv_bfloat16 rG_woh[Dc*Dc],     rG_wol[Dc*Dc];
__device__ __nv_bfloat16 rG_lath[Bc*Sc*Rc], rG_latl[Bc*Sc*Rc];
__device__ __nv_bfloat16 rG_aoh[Bc*Sc*Dc],  rG_aol[Bc*Sc*Dc];

// ---------------- helpers ----------------
__device__ __forceinline__ void rG_mma(float* d, const uint32_t* a, const uint32_t* b) {
    asm volatile(
        "mma.sync.aligned.m16n8k16.row.col.f32.bf16.bf16.f32 "
        "{%0,%1,%2,%3}, {%4,%5,%6,%7}, {%8,%9}, {%0,%1,%2,%3};\n"
        : "+f"(d[0]), "+f"(d[1]), "+f"(d[2]), "+f"(d[3])
        : "r"(a[0]), "r"(a[1]), "r"(a[2]), "r"(a[3]), "r"(b[0]), "r"(b[1]));
}

__device__ __forceinline__ void rG_hilo2(float a, float b, uint32_t& h, uint32_t& l) {
    __nv_bfloat16 ha = __float2bfloat16(a), hb = __float2bfloat16(b);
    __nv_bfloat16 la = __float2bfloat16(a - __bfloat162float(ha));
    __nv_bfloat16 lb = __float2bfloat16(b - __bfloat162float(hb));
    h = (uint32_t)(*(uint16_t*)&ha) | ((uint32_t)(*(uint16_t*)&hb) << 16);
    l = (uint32_t)(*(uint16_t*)&la) | ((uint32_t)(*(uint16_t*)&lb) << 16);
}

// ---------------- fp32 -> bf16 hi/lo split ----------------
__global__ void __launch_bounds__(256) rG_split(const float* __restrict__ src,
                                                __nv_bfloat16* __restrict__ h,
                                                __nv_bfloat16* __restrict__ l,
                                                int n) {
    int i = blockIdx.x * blockDim.x + threadIdx.x;
    if (i >= n) return;
    float a = src[i];
    __nv_bfloat16 hh = __float2bfloat16(a);
    h[i] = hh;
    l[i] = __float2bfloat16(a - __bfloat162float(hh));
}

// ---------------- HMMA split-bf16 GEMM NT (proven R14/R16 structure) --------
#define RG_STRIDE 40
__global__ void __launch_bounds__(256) rG_gemm(
    const __nv_bfloat16* __restrict__ Ah, const __nv_bfloat16* __restrict__ Al,
    const __nv_bfloat16* __restrict__ Bh, const __nv_bfloat16* __restrict__ Bl,
    float* __restrict__ C, __nv_bfloat16* __restrict__ Ch,
    __nv_bfloat16* __restrict__ Cl, int M, int N, int K) {
    __shared__ __nv_bfloat16 sAh[128 * RG_STRIDE], sAl[128 * RG_STRIDE];
    __shared__ __nv_bfloat16 sBh[128 * RG_STRIDE], sBl[128 * RG_STRIDE];

    const int t    = threadIdx.x;
    const int lane = t & 31;
    const int w    = t >> 5;
    const int wm   = w >> 2;
    const int wn   = w & 3;
    const int m0   = blockIdx.y * 128;
    const int n0   = blockIdx.x * 128;
    const int lr   = lane >> 2;
    const int lc   = (lane & 3) * 2;

    float acc[4][4][4];
#pragma unroll
    for (int i = 0; i < 4; i++)
#pragma unroll
        for (int j = 0; j < 4; j++)
#pragma unroll
            for (int k = 0; k < 4; k++) acc[i][j][k] = 0.f;

    for (int k0 = 0; k0 < K; k0 += 32) {
#pragma unroll
        for (int i = 0; i < 2; i++) {
            int idx = t + i * 256;
            int r   = idx >> 2;
            int c8  = (idx & 3) * 8;
            size_t ga = (size_t)(m0 + r) * K + k0 + c8;
            size_t gb = (size_t)(n0 + r) * K + k0 + c8;
            *(uint4*)&sAh[r * RG_STRIDE + c8] = *(const uint4*)&Ah[ga];
            *(uint4*)&sAl[r * RG_STRIDE + c8] = *(const uint4*)&Al[ga];
            *(uint4*)&sBh[r * RG_STRIDE + c8] = *(const uint4*)&Bh[gb];
            *(uint4*)&sBl[r * RG_STRIDE + c8] = *(const uint4*)&Bl[gb];
        }
        __syncthreads();

#pragma unroll
        for (int ks = 0; ks < 2; ks++) {
            const int kk = ks * 16 + lc;
            uint32_t ah[4][4], al[4][4], bh[4][2], bl[4][2];
#pragma unroll
            for (int mt = 0; mt < 4; mt++) {
                int r = wm * 64 + mt * 16 + lr;
                ah[mt][0] = *(const uint32_t*)&sAh[r * RG_STRIDE + kk];
                ah[mt][1] = *(const uint32_t*)&sAh[(r + 8) * RG_STRIDE + kk];
                ah[mt][2] = *(const uint32_t*)&sAh[r * RG_STRIDE + kk + 8];
                ah[mt][3] = *(const uint32_t*)&sAh[(r + 8) * RG_STRIDE + kk + 8];
                al[mt][0] = *(const uint32_t*)&sAl[r * RG_STRIDE + kk];
                al[mt][1] = *(const uint32_t*)&sAl[(r + 8) * RG_STRIDE + kk];
                al[mt][2] = *(const uint32_t*)&sAl[r * RG_STRIDE + kk + 8];
                al[mt][3] = *(const uint32_t*)&sAl[(r + 8) * RG_STRIDE + kk + 8];
            }
#pragma unroll
            for (int nt = 0; nt < 4; nt++) {
                int r = wn * 32 + nt * 8 + lr;
                bh[nt][0] = *(const uint32_t*)&sBh[r * RG_STRIDE + kk];
                bh[nt][1] = *(const uint32_t*)&sBh[r * RG_STRIDE + kk + 8];
                bl[nt][0] = *(const uint32_t*)&sBl[r * RG_STRIDE + kk];
                bl[nt][1] = *(const uint32_t*)&sBl[r * RG_STRIDE + kk + 8];
            }
#pragma unroll
            for (int mt = 0; mt < 4; mt++)
#pragma unroll
                for (int nt = 0; nt < 4; nt++) {
                    rG_mma(acc[mt][nt], ah[mt], bh[nt]);
                    rG_mma(acc[mt][nt], ah[mt], bl[nt]);
                    rG_mma(acc[mt][nt], al[mt], bh[nt]);
                }
        }
        __syncthreads();
    }

#pragma unroll
    for (int mt = 0; mt < 4; mt++) {
#pragma unroll
        for (int nt = 0; nt < 4; nt++) {
#pragma unroll
            for (int half = 0; half < 2; half++) {
                int row = m0 + wm * 64 + mt * 16 + lr + half * 8;
                int col = n0 + wn * 32 + nt * 8 + lc;
                float v0 = acc[mt][nt][half * 2];
                float v1 = acc[mt][nt][half * 2 + 1];
                size_t o = (size_t)row * N + col;
                if (C) { C[o] = v0; C[o + 1] = v1; }
                if (Ch) {
                    __nv_bfloat16 h0 = __float2bfloat16(v0);
                    __nv_bfloat16 h1 = __float2bfloat16(v1);
                    Ch[o] = h0; Ch[o + 1] = h1;
                    Cl[o]     = __float2bfloat16(v0 - __bfloat162float(h0));
                    Cl[o + 1] = __float2bfloat16(v1 - __bfloat162float(h1));
                }
            }
        }
    }
}

// ---------------- rope tables ----------------
__global__ void __launch_bounds__(256) rG_tables() {
    int idx = blockIdx.x * blockDim.x + threadIdx.x;
    if (idx >= Sc * 32) return;
    int s = idx >> 5;
    int j = idx & 31;
    double invf = exp2((double)(-j) * 0.5190512648261504);
    float ang = (float)s * (float)invf;
    double angd = (double)ang;
    double k = rint(angd * 0.15915494309189535);
    float red = (float)(angd - k * 6.283185307179586);
    float c, sn;
    sincosf(red, &c, &sn);
    rG_cos[idx] = c;
    rG_sin[idx] = sn;
}

// ---------------- rope apply once (neg-sin convention, measured) ----------
__global__ void __launch_bounds__(512) rG_rope() {
    int row = blockIdx.x;
    int s   = row & (Sc - 1);
    int t   = threadIdx.x;
    int h   = t >> 5;
    int j   = t & 31;
    float c  = rG_cos[s * 32 + j];
    float sn = rG_sin[s * 32 + j];

    float* qp = rG_q + (size_t)row * Dc + h * HDc + j;
    float a = qp[0], b2 = qp[32];
    qp[0]  = a * c + b2 * sn;
    qp[32] = b2 * c - a * sn;

    float* kp = rG_kv + (size_t)row * (2 * Dc) + h * HDc + j;
    a = kp[0]; b2 = kp[32];
    kp[0]  = a * c + b2 * sn;
    kp[32] = b2 * c - a * sn;
}

// ---------------- block scorer ----------------
__global__ void __launch_bounds__(256) rG_scorer(const float* __restrict__ x,
                                                 const float* __restrict__ w_scorer) {
    int bj = blockIdx.x;
    int b = bj >> 5, j = bj & 31;
    const float* base = x + (size_t)(b * Sc + j * 64) * Dc;
    float sum = 0.f;
    for (int i = threadIdx.x; i < 64 * Dc; i += 256)
        sum += base[i] * w_scorer[i & (Dc - 1)];
    __shared__ float red[256];
    red[threadIdx.x] = sum;
    __syncthreads();
    for (int off = 128; off; off >>= 1) {
        if (threadIdx.x < off) red[threadIdx.x] += red[threadIdx.x + off];
        __syncthreads();
    }
    if (threadIdx.x == 0) rG_scores[bj] = red[0] * (1.0f / 64.0f);
}

// ---------------- top-k ----------------
__global__ void rG_topk() {
    int b = threadIdx.x;
    if (b >= Bc) return;
    float sc[NBc];
    bool used[NBc];
    for (int i = 0; i < NBc; i++) { sc[i] = rG_scores[b * NBc + i]; used[i] = false; }
    int chosen[TOPKc];
    for (int t = 0; t < TOPKc; t++) {
        int best = -1; float bv = -INFINITY;
        for (int i = 0; i < NBc; i++)
            if (!used[i] && sc[i] > bv) { bv = sc[i]; best = i; }
        used[best] = true;
        chosen[t] = best;
    }
    for (int i = 0; i < TOPKc; i++)
        for (int jj = i + 1; jj < TOPKc; jj++)
            if (chosen[jj] < chosen[i]) { int tmp = chosen[i]; chosen[i] = chosen[jj]; chosen[jj] = tmp; }
    for (int i = 0; i < TOPKc; i++) rG_sel[b * TOPKc + i] = chosen[i];
}

// ---------------- v mean over S: two-phase ----------------
__global__ void __launch_bounds__(256) rG_vmean1() {
    int idx = blockIdx.x * 256 + threadIdx.x;      // 0..2047 (b*Dc + d)
    int sy  = blockIdx.y;                           // 0..7, s-chunk of 256
    int b = idx / Dc, d = idx % Dc;
    const float* base = rG_kv + (size_t)b * Sc * (2 * Dc) + Dc + d
                      + (size_t)sy * 256 * (2 * Dc);
    float sum = 0.f;
#pragma unroll 8
    for (int s = 0; s < 256; s++) sum += base[(size_t)s * (2 * Dc)];
    rG_vpart[sy * (Bc * Dc) + idx] = sum;
}
__global__ void __launch_bounds__(256) rG_vmean2() {
    int idx = blockIdx.x * 256 + threadIdx.x;
    float sum = 0.f;
#pragma unroll
    for (int p = 0; p < 8; p++) sum += rG_vpart[p * (Bc * Dc) + idx];
    rG_vmean[idx] = sum * (1.0f / (float)Sc);
}

// ---------------- HMMA flash attention (split-bf16, FA2 fragment flow) -----
// CTA = (b, h, q-tile 64). 128 threads = 4 warps; warp w owns rows 16w..16w+15.
// smem (bf16, row stride 72): Qh Ql Kh Kl (64x[d]), Vh Vl transposed (64[d]x[key]).
__global__ void __launch_bounds__(128) rG_attn_k() {
    extern __shared__ __nv_bfloat16 asm_[];
    __nv_bfloat16* sQh = asm_;
    __nv_bfloat16* sQl = asm_ + 4608;
    __nv_bfloat16* sKh = asm_ + 9216;
    __nv_bfloat16* sKl = asm_ + 13824;
    __nv_bfloat16* sVh = asm_ + 18432;
    __nv_bfloat16* sVl = asm_ + 23040;
    __shared__ int sel_s[TOPKc];

    int lin = blockIdx.x;
    int qt = lin & 31;
    int h  = (lin >> 5) & (Hc - 1);
    int b  = lin >> 9;
    int t  = threadIdx.x;
    int lane = t & 31;
    int w  = t >> 5;

    if (t < TOPKc) sel_s[t] = rG_sel[b * TOPKc + t];
    __syncthreads();
    int min_sel = sel_s[0];

    if (qt < min_sel) {   // fully-masked rows: uniform over all S -> vmean
        for (int idx = t; idx < 4096; idx += 128) {
            int row = idx >> 6, col = idx & 63;
            float val = rG_vmean[b * Dc + h * HDc + col];
            size_t o = (size_t)(b * Sc + qt * 64 + row) * Dc + h * HDc + col;
            __nv_bfloat16 hh = __float2bfloat16(val);
            rG_aoh[o] = hh;
            rG_aol[o] = __float2bfloat16(val - __bfloat162float(hh));
        }
        return;
    }

    // load + split Q (fp32, roped)
    const float* qg = rG_q + (size_t)(b * Sc + qt * 64) * Dc + h * HDc;
#pragma unroll
    for (int i = 0; i < 8; i++) {
        int idx = t + i * 128;
        int row = idx >> 4;
        int c4  = (idx & 15) << 2;
        float4 v = *(const float4*)(qg + (size_t)row * Dc + c4);
        uint32_t h01, l01, h23, l23;
        rG_hilo2(v.x, v.y, h01, l01);
        rG_hilo2(v.z, v.w, h23, l23);
        int off = (row * 72 + c4) >> 1;
        ((uint32_t*)sQh)[off] = h01; ((uint32_t*)sQh)[off + 1] = h23;
        ((uint32_t*)sQl)[off] = l01; ((uint32_t*)sQl)[off + 1] = l23;
    }

    const int lr = lane >> 2;
    const int lc = (lane & 3) * 2;
    const int r0 = w * 16 + lr;
    const int r1 = r0 + 8;

    float m0 = -INFINITY, m1 = -INFINITY, l0 = 0.f, l1 = 0.f;
    float oacc[8][4];
#pragma unroll
    for (int i = 0; i < 8; i++)
#pragma unroll
        for (int j = 0; j < 4; j++) oacc[i][j] = 0.f;

    for (int ib = 0; ib < TOPKc; ib++) {
        int kb = sel_s[ib];
        if (kb > qt) break;
        __syncthreads();   // Q visible (ib=0) / previous block's compute done

        // load + split K; load + split + transpose V
        const float* kg = rG_kv + (size_t)(b * Sc + kb * 64) * (2 * Dc) + h * HDc;
#pragma unroll
        for (int i = 0; i < 8; i++) {
            int idx = t + i * 128;
            int row = idx >> 4;
            int c4  = (idx & 15) << 2;
            float4 kv4 = *(const float4*)(kg + (size_t)row * (2 * Dc) + c4);
            uint32_t h01, l01, h23, l23;
            rG_hilo2(kv4.x, kv4.y, h01, l01);
            rG_hilo2(kv4.z, kv4.w, h23, l23);
            int off = (row * 72 + c4) >> 1;
            ((uint32_t*)sKh)[off] = h01; ((uint32_t*)sKh)[off + 1] = h23;
            ((uint32_t*)sKl)[off] = l01; ((uint32_t*)sKl)[off + 1] = l23;

            float4 vv = *(const float4*)(kg + Dc + (size_t)row * (2 * Dc) + c4);
            float arr[4] = {vv.x, vv.y, vv.z, vv.w};
#pragma unroll
            for (int j = 0; j < 4; j++) {
                int col = c4 + j;
                __nv_bfloat16 hh = __float2bfloat16(arr[j]);
                sVh[col * 72 + row] = hh;
                sVl[col * 72 + row] = __float2bfloat16(arr[j] - __bfloat162float(hh));
            }
        }
        __syncthreads();

        // S = Q K^T (3-term split)
        float sacc[8][4];
#pragma unroll
        for (int i = 0; i < 8; i++)
#pragma unroll
            for (int j = 0; j < 4; j++) sacc[i][j] = 0.f;

        const int arow0 = r0 * 72;
        const int arow1 = r1 * 72;
#pragma unroll
        for (int kc = 0; kc < 4; kc++) {
            int kk = kc * 16 + lc;
            uint32_t qh[4], ql[4];
            qh[0] = *(const uint32_t*)&sQh[arow0 + kk];
            qh[1] = *(const uint32_t*)&sQh[arow1 + kk];
            qh[2] = *(const uint32_t*)&sQh[arow0 + kk + 8];
            qh[3] = *(const uint32_t*)&sQh[arow1 + kk + 8];
            ql[0] = *(const uint32_t*)&sQl[arow0 + kk];
            ql[1] = *(const uint32_t*)&sQl[arow1 + kk];
            ql[2] = *(const uint32_t*)&sQl[arow0 + kk + 8];
            ql[3] = *(const uint32_t*)&sQl[arow1 + kk + 8];
#pragma unroll
            for (int nt = 0; nt < 8; nt++) {
                int kr = (nt * 8 + lr) * 72;
                uint32_t bh[2], bl[2];
                bh[0] = *(const uint32_t*)&sKh[kr + kk];
                bh[1] = *(const uint32_t*)&sKh[kr + kk + 8];
                bl[0] = *(const uint32_t*)&sKl[kr + kk];
                bl[1] = *(const uint32_t*)&sKl[kr + kk + 8];
                rG_mma(sacc[nt], qh, bh);
                rG_mma(sacc[nt], qh, bl);
                rG_mma(sacc[nt], ql, bh);
            }
        }

        // scale + causal mask
        bool diag = (kb == qt);
#pragma unroll
        for (int nt = 0; nt < 8; nt++) {
            int cb = nt * 8 + lc;
            sacc[nt][0] *= 0.125f; sacc[nt][1] *= 0.125f;
            sacc[nt][2] *= 0.125f; sacc[nt][3] *= 0.125f;
            if (diag) {
                if (cb     > r0) sacc[nt][0] = -INFINITY;
                if (cb + 1 > r0) sacc[nt][1] = -INFINITY;
                if (cb     > r1) sacc[nt][2] = -INFINITY;
                if (cb + 1 > r1) sacc[nt][3] = -INFINITY;
            }
        }

        // online softmax on fragments
        float mx0 = -INFINITY, mx1 = -INFINITY;
#pragma unroll
        for (int nt = 0; nt < 8; nt++) {
            mx0 = fmaxf(mx0, fmaxf(sacc[nt][0], sacc[nt][1]));
            mx1 = fmaxf(mx1, fmaxf(sacc[nt][2], sacc[nt][3]));
        }
        mx0 = fmaxf(mx0, __shfl_xor_sync(0xffffffffu, mx0, 1));
        mx0 = fmaxf(mx0, __shfl_xor_sync(0xffffffffu, mx0, 2));
        mx1 = fmaxf(mx1, __shfl_xor_sync(0xffffffffu, mx1, 1));
        mx1 = fmaxf(mx1, __shfl_xor_sync(0xffffffffu, mx1, 2));
        float mn0 = fmaxf(m0, mx0), mn1 = fmaxf(m1, mx1);
        float al0 = __expf(m0 - mn0), al1 = __expf(m1 - mn1);
        float rs0 = 0.f, rs1 = 0.f;
#pragma unroll
        for (int nt = 0; nt < 8; nt++) {
            float p0 = __expf(sacc[nt][0] - mn0);
            float p1 = __expf(sacc[nt][1] - mn0);
            float p2 = __expf(sacc[nt][2] - mn1);
            float p3 = __expf(sacc[nt][3] - mn1);
            sacc[nt][0] = p0; sacc[nt][1] = p1; sacc[nt][2] = p2; sacc[nt][3] = p3;
            rs0 += p0 + p1; rs1 += p2 + p3;
        }
        rs0 += __shfl_xor_sync(0xffffffffu, rs0, 1);
        rs0 += __shfl_xor_sync(0xffffffffu, rs0, 2);
        rs1 += __shfl_xor_sync(0xffffffffu, rs1, 1);
        rs1 += __shfl_xor_sync(0xffffffffu, rs1, 2);
        l0 = l0 * al0 + rs0; m0 = mn0;
        l1 = l1 * al1 + rs1; m1 = mn1;
#pragma unroll
        for (int dt = 0; dt < 8; dt++) {
            oacc[dt][0] *= al0; oacc[dt][1] *= al0;
            oacc[dt][2] *= al1; oacc[dt][3] *= al1;
        }

        // O += P V (3-term split); P fragments straight from sacc (FA2 layout)
#pragma unroll
        for (int kc = 0; kc < 4; kc++) {
            uint32_t ph[4], pl[4];
            rG_hilo2(sacc[2*kc][0],   sacc[2*kc][1],   ph[0], pl[0]);
            rG_hilo2(sacc[2*kc][2],   sacc[2*kc][3],   ph[1], pl[1]);
            rG_hilo2(sacc[2*kc+1][0], sacc[2*kc+1][1], ph[2], pl[2]);
            rG_hilo2(sacc[2*kc+1][2], sacc[2*kc+1][3], ph[3], pl[3]);
            int kk = kc * 16 + lc;
#pragma unroll
            for (int dt = 0; dt < 8; dt++) {
                int dn = (dt * 8 + lr) * 72;
                uint32_t bh[2], bl[2];
                bh[0] = *(const uint32_t*)&sVh[dn + kk];
                bh[1] = *(const uint32_t*)&sVh[dn + kk + 8];
                bl[0] = *(const uint32_t*)&sVl[dn + kk];
                bl[1] = *(const uint32_t*)&sVl[dn + kk + 8];
                rG_mma(oacc[dt], ph, bh);
                rG_mma(oacc[dt], ph, bl);
                rG_mma(oacc[dt], pl, bh);
            }
        }
    }

    // epilogue: O / l -> bf16 hi/lo
    float i0 = 1.f / l0, i1 = 1.f / l1;
    size_t row0 = (size_t)(b * Sc + qt * 64 + r0) * Dc + h * HDc;
    size_t row1 = row0 + 8 * (size_t)Dc;
#pragma unroll
    for (int dt = 0; dt < 8; dt++) {
        int cb = dt * 8 + lc;
        uint32_t hh, ll;
        rG_hilo2(oacc[dt][0] * i0, oacc[dt][1] * i0, hh, ll);
        ((uint32_t*)rG_aoh)[(row0 + cb) >> 1] = hh;
        ((uint32_t*)rG_aol)[(row0 + cb) >> 1] = ll;
        rG_hilo2(oacc[dt][2] * i1, oacc[dt][3] * i1, hh, ll);
        ((uint32_t*)rG_aoh)[(row1 + cb) >> 1] = hh;
        ((uint32_t*)rG_aol)[(row1 + cb) >> 1] = ll;
    }
}

// ---------------- launch ----------------
extern "C" void kernel_launch(void* const* d_in, const int* in_sizes, int n_in,
                              void* d_out, int out_size) {
    const float* x         = (const float*)d_in[0];
    const float* w_q       = (const float*)d_in[1];
    const float* w_kv_down = (const float*)d_in[2];
    const float* w_kv_up   = (const float*)d_in[3];
    const float* w_out     = (const float*)d_in[4];
    const float* w_scorer  = (const float*)d_in[5];
    float* out = (float*)d_out;

    float *q, *kv;
    cudaGetSymbolAddress((void**)&q,  rG_q);
    cudaGetSymbolAddress((void**)&kv, rG_kv);
    __nv_bfloat16 *xh, *xl, *wqh, *wql, *wkdh, *wkdl, *wkuh, *wkul, *woh, *wol,
                  *lath, *latl, *aoh, *aol;
    cudaGetSymbolAddress((void**)&xh,   rG_xh);   cudaGetSymbolAddress((void**)&xl,   rG_xl);
    cudaGetSymbolAddress((void**)&wqh,  rG_wqh);  cudaGetSymbolAddress((void**)&wql,  rG_wql);
    cudaGetSymbolAddress((void**)&wkdh, rG_wkdh); cudaGetSymbolAddress((void**)&wkdl, rG_wkdl);
    cudaGetSymbolAddress((void**)&wkuh, rG_wkuh); cudaGetSymbolAddress((void**)&wkul, rG_wkul);
    cudaGetSymbolAddress((void**)&woh,  rG_woh);  cudaGetSymbolAddress((void**)&wol,  rG_wol);
    cudaGetSymbolAddress((void**)&lath, rG_lath); cudaGetSymbolAddress((void**)&latl, rG_latl);
    cudaGetSymbolAddress((void**)&aoh,  rG_aoh);  cudaGetSymbolAddress((void**)&aol,  rG_aol);

    const int M = Bc * Sc;  // 4096
    auto nb = [](int n) { return (n + 255) / 256; };

    // splits of inputs
    rG_split<<<nb(M * Dc), 256>>>(x, xh, xl, M * Dc);
    rG_split<<<nb(Dc * Dc), 256>>>(w_q, wqh, wql, Dc * Dc);
    rG_split<<<nb(Rc * Dc), 256>>>(w_kv_down, wkdh, wkdl, Rc * Dc);
    rG_split<<<nb(2 * Dc * Rc), 256>>>(w_kv_up, wkuh, wkul, 2 * Dc * Rc);
    rG_split<<<nb(Dc * Dc), 256>>>(w_out, woh, wol, Dc * Dc);

    // projections
    rG_gemm<<<dim3(Dc / 128, M / 128), 256>>>(xh, xl, wqh, wql, q, nullptr, nullptr, M, Dc, Dc);
    rG_gemm<<<dim3(Rc / 128, M / 128), 256>>>(xh, xl, wkdh, wkdl, nullptr, lath, latl, M, Rc, Dc);
    rG_gemm<<<dim3((2 * Dc) / 128, M / 128), 256>>>(lath, latl, wkuh, wkul, kv, nullptr, nullptr, M, 2 * Dc, Rc);

    rG_tables<<<(Sc * 32 + 255) / 256, 256>>>();
    rG_rope<<<M, 512>>>();
    rG_scorer<<<Bc * NBc, 256>>>(x, w_scorer);
    rG_topk<<<1, 32>>>();
    rG_vmean1<<<dim3(Bc * Dc / 256, 8), 256>>>();
    rG_vmean2<<<Bc * Dc / 256, 256>>>();

    // HMMA attention
    int asmem = 27648 * (int)sizeof(__nv_bfloat16);  // 55296 B
    cudaFuncSetAttribute(rG_attn_k, cudaFuncAttributeMaxDynamicSharedMemorySize, asmem);
    rG_attn_k<<<Bc * Hc * (Sc / 64), 128, asmem>>>();

    // out = attn @ w_out^T
    rG_gemm<<<dim3(Dc / 128, M / 128), 256>>>(aoh, aol, woh, wol, out, nullptr, nullptr, M, Dc, Dc);
}